// round 2
// baseline (speedup 1.0000x reference)
#include <cuda_runtime.h>
#include <cuda_bf16.h>

#define N_NODES_MAX 50000
#define N_EDGES_MAX 800000
#define D 64

// Scratch (no cudaMalloc allowed)
__device__ float g_agg [N_NODES_MAX * D];
__device__ float g_h1  [N_NODES_MAX * D];
__device__ int   g_deg [N_NODES_MAX];        // degree histogram
__device__ int   g_off [N_NODES_MAX + 1];    // CSR offsets
__device__ int   g_cur [N_NODES_MAX];        // fill cursors
__device__ int   g_eidx[N_EDGES_MAX];        // src index per CSR slot

// ---------------------------------------------------------------------------
// CSR build step 1: histogram of dst
// ---------------------------------------------------------------------------
__global__ void hist_kernel(const int* __restrict__ dst, int* __restrict__ deg,
                            int n_edges) {
    int i = blockIdx.x * blockDim.x + threadIdx.x;
    int stride = gridDim.x * blockDim.x;
    for (; i < n_edges; i += stride)
        atomicAdd(deg + __ldg(dst + i), 1);
}

// ---------------------------------------------------------------------------
// CSR build step 2: exclusive scan (single block, 1024 threads)
// ---------------------------------------------------------------------------
__global__ __launch_bounds__(1024) void scan_kernel(const int* __restrict__ deg,
                                                    int* __restrict__ off,
                                                    int* __restrict__ cur,
                                                    int n) {
    __shared__ int sums[1024];
    int tid = threadIdx.x;
    int chunk = (n + 1023) / 1024;
    int start = tid * chunk;
    int end = min(start + chunk, n);
    int s = 0;
    for (int i = start; i < end; i++) s += deg[i];
    sums[tid] = s;
    __syncthreads();
    // Hillis-Steele inclusive scan over block sums
    #pragma unroll
    for (int o = 1; o < 1024; o <<= 1) {
        int v = (tid >= o) ? sums[tid - o] : 0;
        __syncthreads();
        sums[tid] += v;
        __syncthreads();
    }
    int run = (tid == 0) ? 0 : sums[tid - 1];
    for (int i = start; i < end; i++) {
        off[i] = run;
        cur[i] = run;
        run += deg[i];
    }
    if (tid == 0) off[n] = sums[1023];
}

// ---------------------------------------------------------------------------
// CSR build step 3: fill — claim slot per edge, record src node
// ---------------------------------------------------------------------------
__global__ void fill_kernel(const int* __restrict__ src,
                            const int* __restrict__ dst,
                            int* __restrict__ cur, int* __restrict__ eidx,
                            int n_edges) {
    int i = blockIdx.x * blockDim.x + threadIdx.x;
    int stride = gridDim.x * blockDim.x;
    for (; i < n_edges; i += stride) {
        int p = atomicAdd(cur + __ldg(dst + i), 1);
        eidx[p] = __ldg(src + i);
    }
}

// ---------------------------------------------------------------------------
// Gather: agg[n] = sum over incoming edges of h[src].
// One warp per node; half-warp per edge (16 lanes x float4 = 64 floats);
// 4 edges in flight per warp (MLP).
// ---------------------------------------------------------------------------
__global__ __launch_bounds__(256) void gather_kernel(
    const float* __restrict__ h, const int* __restrict__ eidx,
    const int* __restrict__ off, float* __restrict__ agg, int n) {
    int warp = (blockIdx.x * blockDim.x + threadIdx.x) >> 5;
    if (warp >= n) return;
    int lane = threadIdx.x & 31;
    int half = lane >> 4;          // 0 or 1: which half-warp
    int hl   = lane & 15;          // lane within half-warp
    int o    = __ldg(off + warp);
    int e    = __ldg(off + warp + 1);

    float4 acc = make_float4(0.f, 0.f, 0.f, 0.f);
    int i = o + half;
    // 4 edges in flight per half-warp (8 per warp window)
    for (; i + 6 < e; i += 8) {
        int s0 = __ldg(eidx + i);
        int s1 = __ldg(eidx + i + 2);
        int s2 = __ldg(eidx + i + 4);
        int s3 = __ldg(eidx + i + 6);
        float4 v0 = *reinterpret_cast<const float4*>(h + (size_t)s0 * D + hl * 4);
        float4 v1 = *reinterpret_cast<const float4*>(h + (size_t)s1 * D + hl * 4);
        float4 v2 = *reinterpret_cast<const float4*>(h + (size_t)s2 * D + hl * 4);
        float4 v3 = *reinterpret_cast<const float4*>(h + (size_t)s3 * D + hl * 4);
        acc.x += v0.x + v1.x + v2.x + v3.x;
        acc.y += v0.y + v1.y + v2.y + v3.y;
        acc.z += v0.z + v1.z + v2.z + v3.z;
        acc.w += v0.w + v1.w + v2.w + v3.w;
    }
    for (; i < e; i += 2) {
        int s = __ldg(eidx + i);
        float4 v = *reinterpret_cast<const float4*>(h + (size_t)s * D + hl * 4);
        acc.x += v.x; acc.y += v.y; acc.z += v.z; acc.w += v.w;
    }
    // combine the two half-warps
    acc.x += __shfl_down_sync(0xffffffffu, acc.x, 16);
    acc.y += __shfl_down_sync(0xffffffffu, acc.y, 16);
    acc.z += __shfl_down_sync(0xffffffffu, acc.z, 16);
    acc.w += __shfl_down_sync(0xffffffffu, acc.w, 16);
    if (half == 0)
        *reinterpret_cast<float4*>(agg + (size_t)warp * D + hl * 4) = acc;
}

// ---------------------------------------------------------------------------
// Y = relu(X @ W + b), X:[n,64] W:[64,64] b:[64]. Thread-per-row, W in smem.
// ---------------------------------------------------------------------------
__global__ __launch_bounds__(256) void gemm_relu_kernel(
    const float* __restrict__ X, const float* __restrict__ W,
    const float* __restrict__ b, float* __restrict__ Y, int n) {
    __shared__ float4 Ws[D * 16];   // W[k][j] row-major, float4 over j
    __shared__ float  bs[D];
    int tid = threadIdx.x;
    for (int i = tid; i < D * 16; i += 256) Ws[i] = reinterpret_cast<const float4*>(W)[i];
    if (tid < D) bs[tid] = b[tid];
    __syncthreads();

    int row = blockIdx.x * 256 + tid;
    if (row >= n) return;
    const float4* xr = reinterpret_cast<const float4*>(X + (size_t)row * D);

    float4 acc[16];
    #pragma unroll
    for (int j = 0; j < 16; j++) acc[j] = reinterpret_cast<const float4*>(bs)[j];

    #pragma unroll 4
    for (int kc = 0; kc < 16; kc++) {
        float4 x = xr[kc];
        int kb = kc * 4;
        #pragma unroll
        for (int j = 0; j < 16; j++) {
            float4 a = acc[j];
            float4 w;
            w = Ws[(kb + 0) * 16 + j];
            a.x += x.x * w.x; a.y += x.x * w.y; a.z += x.x * w.z; a.w += x.x * w.w;
            w = Ws[(kb + 1) * 16 + j];
            a.x += x.y * w.x; a.y += x.y * w.y; a.z += x.y * w.z; a.w += x.y * w.w;
            w = Ws[(kb + 2) * 16 + j];
            a.x += x.z * w.x; a.y += x.z * w.y; a.z += x.z * w.z; a.w += x.z * w.w;
            w = Ws[(kb + 3) * 16 + j];
            a.x += x.w * w.x; a.y += x.w * w.y; a.z += x.w * w.z; a.w += x.w * w.w;
            acc[j] = a;
        }
    }

    float4* yr = reinterpret_cast<float4*>(Y + (size_t)row * D);
    #pragma unroll
    for (int j = 0; j < 16; j++) {
        float4 a = acc[j];
        a.x = fmaxf(a.x, 0.f); a.y = fmaxf(a.y, 0.f);
        a.z = fmaxf(a.z, 0.f); a.w = fmaxf(a.w, 0.f);
        yr[j] = a;
    }
}

// ---------------------------------------------------------------------------
// Layer-2 GEMM + relu + both heads fused.
// ---------------------------------------------------------------------------
__global__ __launch_bounds__(256) void gemm_heads_kernel(
    const float* __restrict__ X, const float* __restrict__ W,
    const float* __restrict__ b,
    const float* __restrict__ Wa, const float* __restrict__ ba,
    const float* __restrict__ Wb, const float* __restrict__ bb,
    float* __restrict__ xa_out, float* __restrict__ xb_out, int n) {
    __shared__ float4 Ws[D * 16];
    __shared__ float  bs[D];
    __shared__ float  Was[D * 2];
    __shared__ float  Wbs[D * 16];
    __shared__ float  bas[2];
    __shared__ float  bbs[16];
    int tid = threadIdx.x;
    for (int i = tid; i < D * 16; i += 256) Ws[i] = reinterpret_cast<const float4*>(W)[i];
    for (int i = tid; i < D * 16; i += 256) Wbs[i] = Wb[i];
    if (tid < D * 2) Was[tid] = Wa[tid];
    if (tid < D) bs[tid] = b[tid];
    if (tid < 2) bas[tid] = ba[tid];
    if (tid < 16) bbs[tid] = bb[tid];
    __syncthreads();

    int row = blockIdx.x * 256 + tid;
    if (row >= n) return;
    const float4* xr = reinterpret_cast<const float4*>(X + (size_t)row * D);

    float4 acc[16];
    #pragma unroll
    for (int j = 0; j < 16; j++) acc[j] = reinterpret_cast<const float4*>(bs)[j];

    #pragma unroll 4
    for (int kc = 0; kc < 16; kc++) {
        float4 x = xr[kc];
        int kb = kc * 4;
        #pragma unroll
        for (int j = 0; j < 16; j++) {
            float4 a = acc[j];
            float4 w;
            w = Ws[(kb + 0) * 16 + j];
            a.x += x.x * w.x; a.y += x.x * w.y; a.z += x.x * w.z; a.w += x.x * w.w;
            w = Ws[(kb + 1) * 16 + j];
            a.x += x.y * w.x; a.y += x.y * w.y; a.z += x.y * w.z; a.w += x.y * w.w;
            w = Ws[(kb + 2) * 16 + j];
            a.x += x.z * w.x; a.y += x.z * w.y; a.z += x.z * w.z; a.w += x.z * w.w;
            w = Ws[(kb + 3) * 16 + j];
            a.x += x.w * w.x; a.y += x.w * w.y; a.z += x.w * w.z; a.w += x.w * w.w;
            acc[j] = a;
        }
    }

    // relu into h (registers)
    float h[D];
    #pragma unroll
    for (int j = 0; j < 16; j++) {
        h[4*j+0] = fmaxf(acc[j].x, 0.f);
        h[4*j+1] = fmaxf(acc[j].y, 0.f);
        h[4*j+2] = fmaxf(acc[j].z, 0.f);
        h[4*j+3] = fmaxf(acc[j].w, 0.f);
    }

    // frame head [2]
    float a0 = bas[0], a1 = bas[1];
    #pragma unroll
    for (int j = 0; j < D; j++) {
        a0 += h[j] * Was[j * 2 + 0];
        a1 += h[j] * Was[j * 2 + 1];
    }
    xa_out[(size_t)row * 2 + 0] = a0;
    xa_out[(size_t)row * 2 + 1] = a1;

    // role head [16]
    float hb[16];
    #pragma unroll
    for (int t = 0; t < 16; t++) hb[t] = bbs[t];
    #pragma unroll
    for (int j = 0; j < D; j++) {
        float hv = h[j];
        #pragma unroll
        for (int t = 0; t < 16; t++) hb[t] += hv * Wbs[j * 16 + t];
    }
    float4* out4 = reinterpret_cast<float4*>(xb_out + (size_t)row * 16);
    #pragma unroll
    for (int q = 0; q < 4; q++)
        out4[q] = make_float4(hb[4*q+0], hb[4*q+1], hb[4*q+2], hb[4*q+3]);
}

// ---------------------------------------------------------------------------
extern "C" void kernel_launch(void* const* d_in, const int* in_sizes, int n_in,
                              void* d_out, int out_size) {
    const float* v   = (const float*)d_in[0];
    const int*   src = (const int*)  d_in[1];
    const int*   dst = (const int*)  d_in[2];
    const float* W1  = (const float*)d_in[3];
    const float* b1  = (const float*)d_in[4];
    const float* W2  = (const float*)d_in[5];
    const float* b2  = (const float*)d_in[6];
    const float* Wa  = (const float*)d_in[7];
    const float* ba  = (const float*)d_in[8];
    const float* Wb  = (const float*)d_in[9];
    const float* bb  = (const float*)d_in[10];

    int n_nodes = in_sizes[0] / D;
    int n_edges = in_sizes[1];

    float* agg;  cudaGetSymbolAddress((void**)&agg,  g_agg);
    float* h1;   cudaGetSymbolAddress((void**)&h1,   g_h1);
    int*   deg;  cudaGetSymbolAddress((void**)&deg,  g_deg);
    int*   off;  cudaGetSymbolAddress((void**)&off,  g_off);
    int*   cur;  cudaGetSymbolAddress((void**)&cur,  g_cur);
    int*   eidx; cudaGetSymbolAddress((void**)&eidx, g_eidx);

    float* xa_out = (float*)d_out;                       // [n, 2]
    float* xb_out = (float*)d_out + (size_t)n_nodes * 2; // [n, 16]

    int edge_blocks   = (n_edges + 255) / 256;
    int gather_blocks = (n_nodes * 32 + 255) / 256;   // 1 warp per node
    int gemm_blocks   = (n_nodes + 255) / 256;

    // ---- CSR build (shared by both layers) ----
    cudaMemsetAsync(deg, 0, n_nodes * sizeof(int));
    hist_kernel<<<min(edge_blocks, 1024), 256>>>(dst, deg, n_edges);
    scan_kernel<<<1, 1024>>>(deg, off, cur, n_nodes);
    fill_kernel<<<min(edge_blocks, 1024), 256>>>(src, dst, cur, eidx, n_edges);

    // ---- Layer 1 ----
    gather_kernel<<<gather_blocks, 256>>>(v, eidx, off, agg, n_nodes);
    gemm_relu_kernel<<<gemm_blocks, 256>>>(agg, W1, b1, h1, n_nodes);

    // ---- Layer 2 + heads ----
    gather_kernel<<<gather_blocks, 256>>>(h1, eidx, off, agg, n_nodes);
    gemm_heads_kernel<<<gemm_blocks, 256>>>(agg, W2, b2, Wa, ba, Wb, bb,
                                            xa_out, xb_out, n_nodes);
}

// round 3
// speedup vs baseline: 1.5541x; 1.5541x over previous
#include <cuda_runtime.h>
#include <cuda_bf16.h>

#define N_NODES_MAX 50000
#define N_EDGES_MAX 800000
#define D 64
#define SCAN_B 1024
#define MAX_SBLK ((N_NODES_MAX + SCAN_B - 1) / SCAN_B)   // 49

// Scratch (no cudaMalloc allowed)
__device__ float g_agg [N_NODES_MAX * D];
__device__ float g_h1  [N_NODES_MAX * D];
__device__ int   g_deg [N_NODES_MAX];
__device__ int   g_off [N_NODES_MAX + 1];
__device__ int   g_cur [N_NODES_MAX];
__device__ int   g_eidx[N_EDGES_MAX];
__device__ int   g_bsum[MAX_SBLK + 1];

// ---------------------------------------------------------------------------
// CSR step 1: histogram of dst (one thread per edge)
// ---------------------------------------------------------------------------
__global__ void hist_kernel(const int* __restrict__ dst, int* __restrict__ deg,
                            int n_edges) {
    int i = blockIdx.x * blockDim.x + threadIdx.x;
    if (i < n_edges) atomicAdd(deg + __ldg(dst + i), 1);
}

// ---------------------------------------------------------------------------
// CSR step 2a: per-block sums of deg (coalesced)
// ---------------------------------------------------------------------------
__global__ __launch_bounds__(SCAN_B) void scanA_kernel(
    const int* __restrict__ deg, int* __restrict__ bsum, int n) {
    __shared__ int s[SCAN_B];
    int tid = threadIdx.x;
    int i = blockIdx.x * SCAN_B + tid;
    s[tid] = (i < n) ? deg[i] : 0;
    __syncthreads();
    #pragma unroll
    for (int o = SCAN_B / 2; o > 0; o >>= 1) {
        if (tid < o) s[tid] += s[tid + o];
        __syncthreads();
    }
    if (tid == 0) bsum[blockIdx.x] = s[0];
}

// ---------------------------------------------------------------------------
// CSR step 2b: exclusive scan of block sums (tiny, one block)
// ---------------------------------------------------------------------------
__global__ __launch_bounds__(64) void scanB_kernel(int* __restrict__ bsum, int nb) {
    __shared__ int s[64];
    int tid = threadIdx.x;
    int v = (tid < nb) ? bsum[tid] : 0;
    s[tid] = v;
    __syncthreads();
    #pragma unroll
    for (int o = 1; o < 64; o <<= 1) {
        int t = (tid >= o) ? s[tid - o] : 0;
        __syncthreads();
        s[tid] += t;
        __syncthreads();
    }
    if (tid < nb) bsum[tid] = s[tid] - v;   // exclusive
}

// ---------------------------------------------------------------------------
// CSR step 2c: per-element offsets = block base + in-block exclusive scan
// ---------------------------------------------------------------------------
__global__ __launch_bounds__(SCAN_B) void scanC_kernel(
    const int* __restrict__ deg, const int* __restrict__ bsum,
    int* __restrict__ off, int* __restrict__ cur, int n) {
    __shared__ int s[SCAN_B];
    int tid = threadIdx.x;
    int i = blockIdx.x * SCAN_B + tid;
    int v = (i < n) ? deg[i] : 0;
    s[tid] = v;
    __syncthreads();
    #pragma unroll
    for (int o = 1; o < SCAN_B; o <<= 1) {
        int t = (tid >= o) ? s[tid - o] : 0;
        __syncthreads();
        s[tid] += t;
        __syncthreads();
    }
    int ex = bsum[blockIdx.x] + s[tid] - v;
    if (i < n) { off[i] = ex; cur[i] = ex; }
    if (i == n - 1) off[n] = ex + v;
}

// ---------------------------------------------------------------------------
// CSR step 3: fill — claim slot per edge, record src node
// ---------------------------------------------------------------------------
__global__ void fill_kernel(const int* __restrict__ src,
                            const int* __restrict__ dst,
                            int* __restrict__ cur, int* __restrict__ eidx,
                            int n_edges) {
    int i = blockIdx.x * blockDim.x + threadIdx.x;
    if (i < n_edges) {
        int p = atomicAdd(cur + __ldg(dst + i), 1);
        eidx[p] = __ldg(src + i);
    }
}

// ---------------------------------------------------------------------------
// Gather: agg[n] = sum over incoming edges of h[src].
// One warp per node; half-warp per edge (16 lanes x float4); 4 edges in
// flight per half-warp.
// ---------------------------------------------------------------------------
__global__ __launch_bounds__(256) void gather_kernel(
    const float* __restrict__ h, const int* __restrict__ eidx,
    const int* __restrict__ off, float* __restrict__ agg, int n) {
    int warp = (blockIdx.x * blockDim.x + threadIdx.x) >> 5;
    if (warp >= n) return;
    int lane = threadIdx.x & 31;
    int half = lane >> 4;
    int hl   = lane & 15;
    int o    = __ldg(off + warp);
    int e    = __ldg(off + warp + 1);

    float4 acc = make_float4(0.f, 0.f, 0.f, 0.f);
    int i = o + half;
    for (; i + 6 < e; i += 8) {
        int s0 = __ldg(eidx + i);
        int s1 = __ldg(eidx + i + 2);
        int s2 = __ldg(eidx + i + 4);
        int s3 = __ldg(eidx + i + 6);
        float4 v0 = *reinterpret_cast<const float4*>(h + (size_t)s0 * D + hl * 4);
        float4 v1 = *reinterpret_cast<const float4*>(h + (size_t)s1 * D + hl * 4);
        float4 v2 = *reinterpret_cast<const float4*>(h + (size_t)s2 * D + hl * 4);
        float4 v3 = *reinterpret_cast<const float4*>(h + (size_t)s3 * D + hl * 4);
        acc.x += v0.x + v1.x + v2.x + v3.x;
        acc.y += v0.y + v1.y + v2.y + v3.y;
        acc.z += v0.z + v1.z + v2.z + v3.z;
        acc.w += v0.w + v1.w + v2.w + v3.w;
    }
    for (; i < e; i += 2) {
        int s = __ldg(eidx + i);
        float4 v = *reinterpret_cast<const float4*>(h + (size_t)s * D + hl * 4);
        acc.x += v.x; acc.y += v.y; acc.z += v.z; acc.w += v.w;
    }
    acc.x += __shfl_down_sync(0xffffffffu, acc.x, 16);
    acc.y += __shfl_down_sync(0xffffffffu, acc.y, 16);
    acc.z += __shfl_down_sync(0xffffffffu, acc.z, 16);
    acc.w += __shfl_down_sync(0xffffffffu, acc.w, 16);
    if (half == 0)
        *reinterpret_cast<float4*>(agg + (size_t)warp * D + hl * 4) = acc;
}

// ---------------------------------------------------------------------------
// Y = relu(X @ W + b). Thread-per-row, W broadcast from smem.
// ---------------------------------------------------------------------------
__global__ __launch_bounds__(256) void gemm_relu_kernel(
    const float* __restrict__ X, const float* __restrict__ W,
    const float* __restrict__ b, float* __restrict__ Y, int n) {
    __shared__ float4 Ws[D * 16];
    __shared__ float  bs[D];
    int tid = threadIdx.x;
    for (int i = tid; i < D * 16; i += 256) Ws[i] = reinterpret_cast<const float4*>(W)[i];
    if (tid < D) bs[tid] = b[tid];
    __syncthreads();

    int row = blockIdx.x * 256 + tid;
    if (row >= n) return;
    const float4* xr = reinterpret_cast<const float4*>(X + (size_t)row * D);

    float4 acc[16];
    #pragma unroll
    for (int j = 0; j < 16; j++) acc[j] = reinterpret_cast<const float4*>(bs)[j];

    #pragma unroll 4
    for (int kc = 0; kc < 16; kc++) {
        float4 x = xr[kc];
        int kb = kc * 4;
        #pragma unroll
        for (int j = 0; j < 16; j++) {
            float4 a = acc[j];
            float4 w;
            w = Ws[(kb + 0) * 16 + j];
            a.x += x.x * w.x; a.y += x.x * w.y; a.z += x.x * w.z; a.w += x.x * w.w;
            w = Ws[(kb + 1) * 16 + j];
            a.x += x.y * w.x; a.y += x.y * w.y; a.z += x.y * w.z; a.w += x.y * w.w;
            w = Ws[(kb + 2) * 16 + j];
            a.x += x.z * w.x; a.y += x.z * w.y; a.z += x.z * w.z; a.w += x.z * w.w;
            w = Ws[(kb + 3) * 16 + j];
            a.x += x.w * w.x; a.y += x.w * w.y; a.z += x.w * w.z; a.w += x.w * w.w;
            acc[j] = a;
        }
    }

    float4* yr = reinterpret_cast<float4*>(Y + (size_t)row * D);
    #pragma unroll
    for (int j = 0; j < 16; j++) {
        float4 a = acc[j];
        a.x = fmaxf(a.x, 0.f); a.y = fmaxf(a.y, 0.f);
        a.z = fmaxf(a.z, 0.f); a.w = fmaxf(a.w, 0.f);
        yr[j] = a;
    }
}

// ---------------------------------------------------------------------------
// Layer-2 GEMM + relu + both heads fused.
// ---------------------------------------------------------------------------
__global__ __launch_bounds__(256) void gemm_heads_kernel(
    const float* __restrict__ X, const float* __restrict__ W,
    const float* __restrict__ b,
    const float* __restrict__ Wa, const float* __restrict__ ba,
    const float* __restrict__ Wb, const float* __restrict__ bb,
    float* __restrict__ xa_out, float* __restrict__ xb_out, int n) {
    __shared__ float4 Ws[D * 16];
    __shared__ float  bs[D];
    __shared__ float  Was[D * 2];
    __shared__ float  Wbs[D * 16];
    __shared__ float  bas[2];
    __shared__ float  bbs[16];
    int tid = threadIdx.x;
    for (int i = tid; i < D * 16; i += 256) Ws[i] = reinterpret_cast<const float4*>(W)[i];
    for (int i = tid; i < D * 16; i += 256) Wbs[i] = Wb[i];
    if (tid < D * 2) Was[tid] = Wa[tid];
    if (tid < D) bs[tid] = b[tid];
    if (tid < 2) bas[tid] = ba[tid];
    if (tid < 16) bbs[tid] = bb[tid];
    __syncthreads();

    int row = blockIdx.x * 256 + tid;
    if (row >= n) return;
    const float4* xr = reinterpret_cast<const float4*>(X + (size_t)row * D);

    float4 acc[16];
    #pragma unroll
    for (int j = 0; j < 16; j++) acc[j] = reinterpret_cast<const float4*>(bs)[j];

    #pragma unroll 4
    for (int kc = 0; kc < 16; kc++) {
        float4 x = xr[kc];
        int kb = kc * 4;
        #pragma unroll
        for (int j = 0; j < 16; j++) {
            float4 a = acc[j];
            float4 w;
            w = Ws[(kb + 0) * 16 + j];
            a.x += x.x * w.x; a.y += x.x * w.y; a.z += x.x * w.z; a.w += x.x * w.w;
            w = Ws[(kb + 1) * 16 + j];
            a.x += x.y * w.x; a.y += x.y * w.y; a.z += x.y * w.z; a.w += x.y * w.w;
            w = Ws[(kb + 2) * 16 + j];
            a.x += x.z * w.x; a.y += x.z * w.y; a.z += x.z * w.z; a.w += x.z * w.w;
            w = Ws[(kb + 3) * 16 + j];
            a.x += x.w * w.x; a.y += x.w * w.y; a.z += x.w * w.z; a.w += x.w * w.w;
            acc[j] = a;
        }
    }

    float h[D];
    #pragma unroll
    for (int j = 0; j < 16; j++) {
        h[4*j+0] = fmaxf(acc[j].x, 0.f);
        h[4*j+1] = fmaxf(acc[j].y, 0.f);
        h[4*j+2] = fmaxf(acc[j].z, 0.f);
        h[4*j+3] = fmaxf(acc[j].w, 0.f);
    }

    float a0 = bas[0], a1 = bas[1];
    #pragma unroll
    for (int j = 0; j < D; j++) {
        a0 += h[j] * Was[j * 2 + 0];
        a1 += h[j] * Was[j * 2 + 1];
    }
    xa_out[(size_t)row * 2 + 0] = a0;
    xa_out[(size_t)row * 2 + 1] = a1;

    float hb[16];
    #pragma unroll
    for (int t = 0; t < 16; t++) hb[t] = bbs[t];
    #pragma unroll
    for (int j = 0; j < D; j++) {
        float hv = h[j];
        #pragma unroll
        for (int t = 0; t < 16; t++) hb[t] += hv * Wbs[j * 16 + t];
    }
    float4* out4 = reinterpret_cast<float4*>(xb_out + (size_t)row * 16);
    #pragma unroll
    for (int q = 0; q < 4; q++)
        out4[q] = make_float4(hb[4*q+0], hb[4*q+1], hb[4*q+2], hb[4*q+3]);
}

// ---------------------------------------------------------------------------
extern "C" void kernel_launch(void* const* d_in, const int* in_sizes, int n_in,
                              void* d_out, int out_size) {
    const float* v   = (const float*)d_in[0];
    const int*   src = (const int*)  d_in[1];
    const int*   dst = (const int*)  d_in[2];
    const float* W1  = (const float*)d_in[3];
    const float* b1  = (const float*)d_in[4];
    const float* W2  = (const float*)d_in[5];
    const float* b2  = (const float*)d_in[6];
    const float* Wa  = (const float*)d_in[7];
    const float* ba  = (const float*)d_in[8];
    const float* Wb  = (const float*)d_in[9];
    const float* bb  = (const float*)d_in[10];

    int n_nodes = in_sizes[0] / D;
    int n_edges = in_sizes[1];

    float* agg;  cudaGetSymbolAddress((void**)&agg,  g_agg);
    float* h1;   cudaGetSymbolAddress((void**)&h1,   g_h1);
    int*   deg;  cudaGetSymbolAddress((void**)&deg,  g_deg);
    int*   off;  cudaGetSymbolAddress((void**)&off,  g_off);
    int*   cur;  cudaGetSymbolAddress((void**)&cur,  g_cur);
    int*   eidx; cudaGetSymbolAddress((void**)&eidx, g_eidx);
    int*   bsum; cudaGetSymbolAddress((void**)&bsum, g_bsum);

    float* xa_out = (float*)d_out;
    float* xb_out = (float*)d_out + (size_t)n_nodes * 2;

    int edge_blocks   = (n_edges + 255) / 256;
    int scan_blocks   = (n_nodes + SCAN_B - 1) / SCAN_B;
    int gather_blocks = (n_nodes * 32 + 255) / 256;
    int gemm_blocks   = (n_nodes + 255) / 256;

    // ---- CSR build (shared by both layers) ----
    cudaMemsetAsync(deg, 0, n_nodes * sizeof(int));
    hist_kernel <<<edge_blocks, 256>>>(dst, deg, n_edges);
    scanA_kernel<<<scan_blocks, SCAN_B>>>(deg, bsum, n_nodes);
    scanB_kernel<<<1, 64>>>(bsum, scan_blocks);
    scanC_kernel<<<scan_blocks, SCAN_B>>>(deg, bsum, off, cur, n_nodes);
    fill_kernel <<<edge_blocks, 256>>>(src, dst, cur, eidx, n_edges);

    // ---- Layer 1 ----
    gather_kernel<<<gather_blocks, 256>>>(v, eidx, off, agg, n_nodes);
    gemm_relu_kernel<<<gemm_blocks, 256>>>(agg, W1, b1, h1, n_nodes);

    // ---- Layer 2 + heads ----
    gather_kernel<<<gather_blocks, 256>>>(h1, eidx, off, agg, n_nodes);
    gemm_heads_kernel<<<gemm_blocks, 256>>>(agg, W2, b2, Wa, ba, Wb, bb,
                                            xa_out, xb_out, n_nodes);
}